// round 5
// baseline (speedup 1.0000x reference)
#include <cuda_runtime.h>
#include <cuda_bf16.h>

// VQ: nearest-codebook lookup.
// Phase 1: fused fp32(f32x2) GEMM + top-2 argmin per row.
// Phase 2: exact fp64 distances on the top-2, each rounded once to fp32.
//          Bit-equal floats => the reference's fp32 dists tie => lower index
//          (jnp.argmin first-occurrence). Else exact strict order.
// x: (N=131072, C=256), code_book: (K=1024, C=256)
// out: zq (N*C fp32) [+ indices (N) as fp32 if out_size covers it]

#define C_DIM 256
#define BM 128
#define BN 128
#define KC 16
#define BMP 132   // padded row stride for Xs [c][row]
#define BNP 132   // padded row stride for Es [c][code]
#define MAXROWS 131072
#define TIE_GUARD 2e-6   // catches a true ref-tie straddling an fp32 bin edge

__device__ float g_esq[8192];
__device__ int2  g_top2[MAXROWS];   // per-row (best_idx, second_idx) from fp32 pass

// e_sq[k] = sum(cb[k]*cb[k]) — fp32, used only for phase-1 candidate ranking
__global__ void esq_kernel(const float* __restrict__ cb, int K) {
    int k = blockIdx.x * blockDim.x + threadIdx.x;
    if (k < K) {
        const float* p = cb + (size_t)k * C_DIM;
        float s = 0.0f;
        for (int c = 0; c < C_DIM; ++c) s = __fadd_rn(s, __fmul_rn(p[c], p[c]));
        g_esq[k] = s;
    }
}

__device__ __forceinline__ unsigned long long dup_f32(float a) {
    unsigned long long d;
    unsigned int u = __float_as_uint(a);
    asm("mov.b64 %0, {%1, %1};" : "=l"(d) : "r"(u));
    return d;
}
__device__ __forceinline__ void fma2(unsigned long long& acc, unsigned long long a, unsigned long long b) {
    asm("fma.rn.f32x2 %0, %1, %2, %0;" : "+l"(acc) : "l"(a), "l"(b));
}
__device__ __forceinline__ void unpack2(unsigned long long v, float& lo, float& hi) {
    unsigned int a, b;
    asm("mov.b64 {%0, %1}, %2;" : "=r"(a), "=r"(b) : "l"(v));
    lo = __uint_as_float(a);
    hi = __uint_as_float(b);
}

__global__ __launch_bounds__(256, 1)
void vq_kernel(const float* __restrict__ x, const float* __restrict__ cb,
               int NROWS, int K)
{
    extern __shared__ float sm[];
    float* Xs   = sm;                          // [256][BMP] = x tile transposed
    float* Es   = sm + C_DIM * BMP;            // [2][KC][BNP] double-buffered code chunk
    float* xsqs = Es + 2 * KC * BNP;           // [128]

    const int tid = threadIdx.x;
    const int tx = tid & 15;        // code-dim thread coord (0..15)
    const int ty = tid >> 4;        // row-dim thread coord (0..15)
    const int row0 = blockIdx.x * BM;

    // ---- load X tile transposed: Xs[c][r] = x[row0+r][c] ----
    {
        const int r = tid & 127;
        const int g = tid >> 7;
        const bool valid = (row0 + r) < NROWS;
        const float* xp = x + (size_t)(row0 + r) * C_DIM;
        for (int c = g * 4; c < C_DIM; c += 8) {
            float4 v;
            if (valid) v = *(const float4*)(xp + c);
            else { v.x = v.y = v.z = v.w = 0.0f; }
            Xs[(c + 0) * BMP + r] = v.x;
            Xs[(c + 1) * BMP + r] = v.y;
            Xs[(c + 2) * BMP + r] = v.z;
            Xs[(c + 3) * BMP + r] = v.w;
        }
    }
    __syncthreads();

    // ---- x_sq per row (phase-1 ranking only) ----
    if (tid < BM) {
        float s = 0.0f;
        for (int c = 0; c < C_DIM; ++c) {
            float v = Xs[c * BMP + tid];
            s = __fadd_rn(s, __fmul_rn(v, v));
        }
        xsqs[tid] = s;
    }

    float bestd[8], secd[8];
    int besti[8], seci[8];
#pragma unroll
    for (int i = 0; i < 8; ++i) {
        bestd[i] = 3.4e38f; besti[i] = 0;
        secd[i]  = 3.4e38f; seci[i]  = 1;
    }

    const int j = tid >> 1;
    const int h = tid & 1;

    const int ntiles = K / BN;
    for (int ct = 0; ct < ntiles; ++ct) {
        const int n0 = ct * BN;
        unsigned long long acc[8][4];
#pragma unroll
        for (int i = 0; i < 8; ++i)
#pragma unroll
            for (int q = 0; q < 4; ++q) acc[i][q] = 0ULL;

        const float* ebase = cb + (size_t)(n0 + j) * C_DIM + h * 8;

        // preload chunk 0 -> buf 0 (transposed: Es[c_local][code])
        {
            float4 e0 = *(const float4*)(ebase + 0);
            float4 e1 = *(const float4*)(ebase + 4);
            float* E0 = Es;
            const int cl = h * 8;
            E0[(cl + 0) * BNP + j] = e0.x;
            E0[(cl + 1) * BNP + j] = e0.y;
            E0[(cl + 2) * BNP + j] = e0.z;
            E0[(cl + 3) * BNP + j] = e0.w;
            E0[(cl + 4) * BNP + j] = e1.x;
            E0[(cl + 5) * BNP + j] = e1.y;
            E0[(cl + 6) * BNP + j] = e1.z;
            E0[(cl + 7) * BNP + j] = e1.w;
        }
        __syncthreads();

        int p = 0;
#pragma unroll 1
        for (int kc = 0; kc < C_DIM / KC; ++kc) {
            float4 e0, e1;
            const bool pf = (kc < C_DIM / KC - 1);
            if (pf) {
                const float* ep = ebase + (kc + 1) * KC;
                e0 = *(const float4*)(ep + 0);
                e1 = *(const float4*)(ep + 4);
            }
            const float* Ecur = Es + p * KC * BNP;

#pragma unroll
            for (int kk = 0; kk < KC; ++kk) {
                const float* xrow = &Xs[(kc * KC + kk) * BMP + ty * 8];
                float4 a0 = *(const float4*)(xrow + 0);
                float4 a1 = *(const float4*)(xrow + 4);
                const ulonglong2* bp = (const ulonglong2*)&Ecur[kk * BNP + tx * 8];
                ulonglong2 b01 = bp[0];
                ulonglong2 b23 = bp[1];
                unsigned long long bb0 = b01.x, bb1 = b01.y, bb2 = b23.x, bb3 = b23.y;

                unsigned long long ad[8];
                ad[0] = dup_f32(a0.x); ad[1] = dup_f32(a0.y);
                ad[2] = dup_f32(a0.z); ad[3] = dup_f32(a0.w);
                ad[4] = dup_f32(a1.x); ad[5] = dup_f32(a1.y);
                ad[6] = dup_f32(a1.z); ad[7] = dup_f32(a1.w);

#pragma unroll
                for (int i = 0; i < 8; ++i) {
                    fma2(acc[i][0], ad[i], bb0);
                    fma2(acc[i][1], ad[i], bb1);
                    fma2(acc[i][2], ad[i], bb2);
                    fma2(acc[i][3], ad[i], bb3);
                }
            }

            if (pf) {
                float* Enx = Es + (p ^ 1) * KC * BNP;
                const int cl = h * 8;
                Enx[(cl + 0) * BNP + j] = e0.x;
                Enx[(cl + 1) * BNP + j] = e0.y;
                Enx[(cl + 2) * BNP + j] = e0.z;
                Enx[(cl + 3) * BNP + j] = e0.w;
                Enx[(cl + 4) * BNP + j] = e1.x;
                Enx[(cl + 5) * BNP + j] = e1.y;
                Enx[(cl + 6) * BNP + j] = e1.z;
                Enx[(cl + 7) * BNP + j] = e1.w;
            }
            __syncthreads();
            p ^= 1;
        }

        // ---- epilogue: dist = (x_sq + e_sq) - 2*dot, running top-2 ----
#pragma unroll
        for (int i = 0; i < 8; ++i) {
            const float xq = xsqs[ty * 8 + i];
#pragma unroll
            for (int q = 0; q < 4; ++q) {
                float dlo, dhi;
                unpack2(acc[i][q], dlo, dhi);
                const int n = n0 + tx * 8 + q * 2;
                float s0 = __fsub_rn(__fadd_rn(xq, g_esq[n]),     __fmul_rn(2.0f, dlo));
                float s1 = __fsub_rn(__fadd_rn(xq, g_esq[n + 1]), __fmul_rn(2.0f, dhi));
                if (s0 < bestd[i]) {
                    secd[i] = bestd[i]; seci[i] = besti[i];
                    bestd[i] = s0; besti[i] = n;
                } else if (s0 < secd[i]) { secd[i] = s0; seci[i] = n; }
                if (s1 < bestd[i]) {
                    secd[i] = bestd[i]; seci[i] = besti[i];
                    bestd[i] = s1; besti[i] = n + 1;
                } else if (s1 < secd[i]) { secd[i] = s1; seci[i] = n + 1; }
            }
        }
    }

    // ---- cross-thread top-2 merge (overlay on Xs region, now dead) ----
    __syncthreads();
    float* rd = sm;                        // [128][32] dists (best,sec interleaved)
    int* ri = (int*)(sm + BM * 32);        // [128][32] indices
#pragma unroll
    for (int i = 0; i < 8; ++i) {
        const int r = ty * 8 + i;
        rd[r * 32 + tx * 2 + 0] = bestd[i];
        rd[r * 32 + tx * 2 + 1] = secd[i];
        ri[r * 32 + tx * 2 + 0] = besti[i];
        ri[r * 32 + tx * 2 + 1] = seci[i];
    }
    __syncthreads();
    if (tid < BM) {
        float b1 = 3.4e38f, b2 = 3.4e38f;
        int j1 = 0, j2 = 1;
        for (int t = 0; t < 32; ++t) {
            float d = rd[tid * 32 + t];
            int ii = ri[tid * 32 + t];
            if (d < b1 || (d == b1 && ii < j1)) {
                b2 = b1; j2 = j1; b1 = d; j1 = ii;
            } else if (d < b2 || (d == b2 && ii < j2)) {
                b2 = d; j2 = ii;
            }
        }
        const int row = row0 + tid;
        if (row < NROWS) g_top2[row] = make_int2(j1, j2);
    }
}

// ---- phase 2: exact fp64 dists; fp32 bin-equality => ref tie => min index ----
__global__ __launch_bounds__(128, 8)
void refine_kernel(const float* __restrict__ x, const float* __restrict__ cb,
                   float* __restrict__ zq, float* __restrict__ idx_out,
                   int NROWS, int write_idx)
{
    const int warp = threadIdx.x >> 5;
    const int lane = threadIdx.x & 31;
    const int row = blockIdx.x * 4 + warp;
    if (row >= NROWS) return;

    const int2 cand = g_top2[row];
    const float* xp  = x  + (size_t)row * C_DIM + lane * 8;
    const float* e1p = cb + (size_t)cand.x * C_DIM + lane * 8;
    const float* e2p = cb + (size_t)cand.y * C_DIM + lane * 8;

    float4 xa = *(const float4*)(xp);
    float4 xb = *(const float4*)(xp + 4);
    float4 u1a = *(const float4*)(e1p);
    float4 u1b = *(const float4*)(e1p + 4);
    float4 u2a = *(const float4*)(e2p);
    float4 u2b = *(const float4*)(e2p + 4);

    // exact (to fp64) squared distances, difference form
    double d1 = 0.0, d2 = 0.0;
    {
        const float xs[8] = {xa.x, xa.y, xa.z, xa.w, xb.x, xb.y, xb.z, xb.w};
        const float e1[8] = {u1a.x, u1a.y, u1a.z, u1a.w, u1b.x, u1b.y, u1b.z, u1b.w};
        const float e2[8] = {u2a.x, u2a.y, u2a.z, u2a.w, u2b.x, u2b.y, u2b.z, u2b.w};
#pragma unroll
        for (int t = 0; t < 8; ++t) {
            double t1 = (double)xs[t] - (double)e1[t];
            double t2 = (double)xs[t] - (double)e2[t];
            d1 = fma(t1, t1, d1);
            d2 = fma(t2, t2, d2);
        }
    }
#pragma unroll
    for (int o = 16; o > 0; o >>= 1) {
        d1 += __shfl_down_sync(0xffffffffu, d1, o);
        d2 += __shfl_down_sync(0xffffffffu, d2, o);
    }
    int chosen;
    if (lane == 0) {
        // Round once to fp32: bit-equal => same representable bin => the
        // reference's fp32 dists tie => jnp.argmin takes the lower index.
        float f1 = (float)d1;
        float f2 = (float)d2;
        if (f1 == f2 || fabs(d1 - d2) < (double)TIE_GUARD) {
            chosen = min(cand.x, cand.y);
        } else {
            chosen = (f1 < f2) ? cand.x : cand.y;
        }
    }
    chosen = __shfl_sync(0xffffffffu, chosen, 0);

    // write zq row from chosen codebook entry
    const float* ep = cb + (size_t)chosen * C_DIM + lane * 8;
    float* op = zq + (size_t)row * C_DIM + lane * 8;
    *(float4*)(op)     = *(const float4*)(ep);
    *(float4*)(op + 4) = *(const float4*)(ep + 4);

    if (write_idx && lane == 0) idx_out[row] = (float)chosen;
}

extern "C" void kernel_launch(void* const* d_in, const int* in_sizes, int n_in,
                              void* d_out, int out_size) {
    const float* x  = (const float*)d_in[0];
    const float* cb = (const float*)d_in[1];
    float* out = (float*)d_out;

    const int NROWS = in_sizes[0] / C_DIM;
    const int K     = in_sizes[1] / C_DIM;

    esq_kernel<<<(K + 255) / 256, 256>>>(cb, K);

    const size_t smem = (size_t)(C_DIM * BMP + 2 * KC * BNP + BM) * sizeof(float);
    cudaFuncSetAttribute(vq_kernel, cudaFuncAttributeMaxDynamicSharedMemorySize, (int)smem);

    const int grid = (NROWS + BM - 1) / BM;
    vq_kernel<<<grid, 256, smem>>>(x, cb, NROWS, K);

    const int write_idx = (out_size >= NROWS * C_DIM + NROWS) ? 1 : 0;
    refine_kernel<<<(NROWS + 3) / 4, 128>>>(x, cb, out, out + (size_t)NROWS * C_DIM,
                                            NROWS, write_idx);
}

// round 11
// speedup vs baseline: 1.9820x; 1.9820x over previous
#include <cuda_runtime.h>
#include <cuda_bf16.h>
#include <cstdint>

// VQ: nearest-codebook lookup.
// Phase 1: mma.sync bf16 2-plane split GEMM (3 products) -> top-2 per row.
// Phase 2: exact fp64 on top-2 + fp32-bin tie emulation (verified rel_err 0.0).
// x: (N=131072, C=256), code_book: (K=1024, C=256)

#define C_DIM 256
#define TILE_M 128
#define MAXROWS 131072
#define MAXK 1024
#define TIE_GUARD 2e-6

// smem map (bytes)
#define SM_ESQ 0                    // 4KB
#define SM_A   8192                 // 2 planes x 128 rows x 512B = 131072
#define SM_B   (8192 + 131072)      // 2 bufs x 32KB = 65536
#define SM_TOTAL (SM_B + 65536)     // 204800
#define SM_MERGE SM_B

__device__ float          g_esq[MAXK];
__device__ int2           g_top2[MAXROWS];
__device__ __nv_bfloat16  g_cb0[MAXK * C_DIM];
__device__ __nv_bfloat16  g_cb1[MAXK * C_DIM];

__device__ __forceinline__ uint32_t smem_u32(const void* p) {
    uint32_t a;
    asm("{ .reg .u64 t; cvta.to.shared.u64 t, %1; cvt.u32.u64 %0, t; }" : "=r"(a) : "l"(p));
    return a;
}
__device__ __forceinline__ void ldsm4(uint32_t* r, uint32_t addr) {
    asm volatile("ldmatrix.sync.aligned.m8n8.x4.shared.b16 {%0,%1,%2,%3}, [%4];"
        : "=r"(r[0]), "=r"(r[1]), "=r"(r[2]), "=r"(r[3]) : "r"(addr));
}
__device__ __forceinline__ void mma16816(float* d, const uint32_t* a, uint32_t b0, uint32_t b1) {
    asm volatile("mma.sync.aligned.m16n8k16.row.col.f32.bf16.bf16.f32 "
        "{%0,%1,%2,%3}, {%4,%5,%6,%7}, {%8,%9}, {%0,%1,%2,%3};"
        : "+f"(d[0]), "+f"(d[1]), "+f"(d[2]), "+f"(d[3])
        : "r"(a[0]), "r"(a[1]), "r"(a[2]), "r"(a[3]), "r"(b0), "r"(b1));
}
__device__ __forceinline__ void cp_async16(uint32_t dst, const void* src) {
    asm volatile("cp.async.cg.shared.global [%0], [%1], 16;" :: "r"(dst), "l"(src));
}
#define CP_COMMIT() asm volatile("cp.async.commit_group;" ::: "memory")
#define CP_WAIT1()  asm volatile("cp.async.wait_group 1;" ::: "memory")
#define CP_WAIT0()  asm volatile("cp.async.wait_group 0;" ::: "memory")

__device__ __forceinline__ uint32_t pk(__nv_bfloat16 lo, __nv_bfloat16 hi) {
    return ((uint32_t)__bfloat16_as_ushort(hi) << 16) | (uint32_t)__bfloat16_as_ushort(lo);
}

// ---------------- prep: e_sq + codebook bf16 planes (warp per code) ----------------
__global__ void prep_cb(const float* __restrict__ cb, int K) {
    int k = blockIdx.x * 8 + (threadIdx.x >> 5);
    int lane = threadIdx.x & 31;
    if (k >= K) return;
    const float* p = cb + (size_t)k * C_DIM;
    float s = 0.0f;
    for (int c = lane; c < C_DIM; c += 32) {
        float f = p[c];
        s = fmaf(f, f, s);
        __nv_bfloat16 b0 = __float2bfloat16(f);
        float r = f - __bfloat162float(b0);
        g_cb0[(size_t)k * C_DIM + c] = b0;
        g_cb1[(size_t)k * C_DIM + c] = __float2bfloat16(r);
    }
#pragma unroll
    for (int o = 16; o > 0; o >>= 1) s += __shfl_down_sync(0xffffffffu, s, o);
    if (lane == 0) g_esq[k] = s;
}

// chunk = (tile, kc): 128 codes x 64 k x 2 planes = 32KB
__device__ __forceinline__ void load_chunk(uint32_t sb, int ch, int tid) {
    const int tile = ch >> 2, kc = ch & 3;
    const uint32_t dstbase = sb + SM_B + (uint32_t)(ch & 1) * 32768u;
#pragma unroll
    for (int it = 0; it < 8; ++it) {
        int i = tid + it * 256;       // 0..2047
        int pl = i >> 10;
        int rem = i & 1023;
        int n = rem >> 3;
        int jj = rem & 7;
        const char* src = (const char*)(pl ? g_cb1 : g_cb0)
                        + ((size_t)(tile * 128 + n) * C_DIM + kc * 64 + jj * 8) * 2;
        uint32_t dst = dstbase + (uint32_t)(pl * 16384 + n * 128 + (((jj ^ (n & 7)) << 4)));
        cp_async16(dst, src);
    }
}

// ---------------- phase 1 ----------------
__global__ __launch_bounds__(256, 1)
void vq_main(const float* __restrict__ x, int NROWS, int K)
{
    extern __shared__ char smem[];
    const uint32_t sb = smem_u32(smem);
    float* esq_s = (float*)(smem + SM_ESQ);
    const int tid = threadIdx.x;
    const int wid = tid >> 5, l = tid & 31;
    const int Wm = wid >> 1, Wn = wid & 1;
    const int row0 = blockIdx.x * TILE_M;
    const int nch = (K / 128) * 4;      // 32 for K=1024

    for (int i = tid; i < K; i += 256) esq_s[i] = g_esq[i];

    // prefetch chunk 0 while we build A planes
    load_chunk(sb, 0, tid);
    CP_COMMIT();

    // ---- build A planes in smem (swizzled) ----
#pragma unroll 4
    for (int it = 0; it < 32; ++it) {
        int i4 = tid + it * 256;         // 8192 float4s = 128 rows x 64
        int r = i4 >> 6;
        int c0 = (i4 & 63) * 4;
        int rr = row0 + r; if (rr >= NROWS) rr = NROWS - 1;
        float4 v = *(const float4*)(x + (size_t)rr * C_DIM + c0);
        __nv_bfloat16 p0 = __float2bfloat16(v.x), p1 = __float2bfloat16(v.y),
                      p2 = __float2bfloat16(v.z), p3 = __float2bfloat16(v.w);
        __nv_bfloat16 q0 = __float2bfloat16(v.x - __bfloat162float(p0));
        __nv_bfloat16 q1 = __float2bfloat16(v.y - __bfloat162float(p1));
        __nv_bfloat16 q2 = __float2bfloat16(v.z - __bfloat162float(p2));
        __nv_bfloat16 q3 = __float2bfloat16(v.w - __bfloat162float(p3));
        uint32_t byte = (uint32_t)(r * 512 + (((c0 >> 3) ^ (r & 7)) << 4) + (c0 & 7) * 2);
        *(uint32_t*)(smem + SM_A + byte)             = pk(p0, p1);
        *(uint32_t*)(smem + SM_A + byte + 4)         = pk(p2, p3);
        *(uint32_t*)(smem + SM_A + 65536 + byte)     = pk(q0, q1);
        *(uint32_t*)(smem + SM_A + 65536 + byte + 4) = pk(q2, q3);
    }

    // ---- per-lane ldmatrix address bases ----
    uint32_t aBase[2], a7[2];
    const uint32_t jAadd = (uint32_t)((l >> 4) & 1);
#pragma unroll
    for (int mt = 0; mt < 2; ++mt) {
        int rA = Wm * 32 + mt * 16 + ((l >> 3) & 1) * 8 + (l & 7);
        aBase[mt] = sb + SM_A + (uint32_t)rA * 512u;
        a7[mt] = (uint32_t)(rA & 7) << 4;
    }
    uint32_t bOff[4], b7[4];
    const uint32_t jBadd = (uint32_t)((l >> 3) & 1);
#pragma unroll
    for (int ntp = 0; ntp < 4; ++ntp) {
        int nB = Wn * 64 + ntp * 16 + ((l >> 4) & 1) * 8 + (l & 7);
        bOff[ntp] = (uint32_t)nB * 128u;
        b7[ntp] = (uint32_t)(nB & 7) << 4;
    }

    float acc[2][8][4];
    float bd[4], sd[4];
    int bi[4], si[4];
#pragma unroll
    for (int s = 0; s < 4; ++s) { bd[s] = 3.4e38f; sd[s] = 3.4e38f; bi[s] = 0; si[s] = 1; }

    for (int ch = 0; ch < nch; ++ch) {
        if (ch + 1 < nch) { load_chunk(sb, ch + 1, tid); CP_COMMIT(); CP_WAIT1(); }
        else              { CP_WAIT0(); }
        __syncthreads();

        const int kc = ch & 3, tile = ch >> 2;
        if (kc == 0) {
#pragma unroll
            for (int mt = 0; mt < 2; ++mt)
#pragma unroll
                for (int nt = 0; nt < 8; ++nt)
#pragma unroll
                    for (int q = 0; q < 4; ++q) acc[mt][nt][q] = 0.0f;
        }
        const uint32_t bufb = sb + SM_B + (uint32_t)(ch & 1) * 32768u;

#pragma unroll
        for (int ks = 0; ks < 4; ++ks) {
            uint32_t a[2][2][4];
            const uint32_t jxA = (uint32_t)((kc * 8 + ks * 2 + jAadd) << 4);
#pragma unroll
            for (int pl = 0; pl < 2; ++pl)
#pragma unroll
                for (int mt = 0; mt < 2; ++mt)
                    ldsm4(a[pl][mt], aBase[mt] + (uint32_t)pl * 65536u + (jxA ^ a7[mt]));

            const uint32_t jxB = (uint32_t)((ks * 2 + jBadd) << 4);
#pragma unroll
            for (int ntp = 0; ntp < 4; ++ntp) {
                uint32_t b0f[4], b1f[4];
                ldsm4(b0f, bufb + bOff[ntp] + (jxB ^ b7[ntp]));
                ldsm4(b1f, bufb + 16384u + bOff[ntp] + (jxB ^ b7[ntp]));
#pragma unroll
                for (int mt = 0; mt < 2; ++mt) {
#pragma unroll
                    for (int sub = 0; sub < 2; ++sub) {
                        float* d = acc[mt][ntp * 2 + sub];
                        mma16816(d, a[0][mt], b0f[2 * sub], b0f[2 * sub + 1]);  // A0*B0
                        mma16816(d, a[0][mt], b1f[2 * sub], b1f[2 * sub + 1]);  // A0*B1
                        mma16816(d, a[1][mt], b0f[2 * sub], b0f[2 * sub + 1]);  // A1*B0
                    }
                }
            }
        }

        if (kc == 3) {
            // top-2 update from register accumulators
            const int cbase = tile * 128 + Wn * 64 + 2 * (l & 3);
#pragma unroll
            for (int mt = 0; mt < 2; ++mt) {
#pragma unroll
                for (int rh = 0; rh < 2; ++rh) {
                    const int s = mt * 2 + rh;
                    float lbd = bd[s], lsd = sd[s];
                    int lbi = bi[s], lsi = si[s];
#pragma unroll
                    for (int nt = 0; nt < 8; ++nt) {
                        const int code = cbase + nt * 8;
                        float d0 = fmaf(-2.0f, acc[mt][nt][rh * 2 + 0], esq_s[code]);
                        float d1 = fmaf(-2.0f, acc[mt][nt][rh * 2 + 1], esq_s[code + 1]);
                        if (d0 < lbd) { lsd = lbd; lsi = lbi; lbd = d0; lbi = code; }
                        else if (d0 < lsd) { lsd = d0; lsi = code; }
                        if (d1 < lbd) { lsd = lbd; lsi = lbi; lbd = d1; lbi = code + 1; }
                        else if (d1 < lsd) { lsd = d1; lsi = code + 1; }
                    }
                    bd[s] = lbd; sd[s] = lsd; bi[s] = lbi; si[s] = lsi;
                }
            }
        }
        __syncthreads();
    }

    // ---- merge: 8 sources per row -> top-2 ----
    float* md = (float*)(smem + SM_MERGE);          // [128][8][2]
    int*   mi = (int*)(smem + SM_MERGE + 8192);
#pragma unroll
    for (int mt = 0; mt < 2; ++mt) {
#pragma unroll
        for (int rh = 0; rh < 2; ++rh) {
            const int s = mt * 2 + rh;
            const int r = Wm * 32 + mt * 16 + rh * 8 + (l >> 2);
            const int slot = (l & 3) * 2 + Wn;
            md[(r * 8 + slot) * 2 + 0] = bd[s];
            md[(r * 8 + slot) * 2 + 1] = sd[s];
            mi[(r * 8 + slot) * 2 + 0] = bi[s];
            mi[(r * 8 + slot) * 2 + 1] = si[s];
        }
    }
    __syncthreads();
    if (tid < TILE_M) {
        float b1 = 3.4e38f, b2 = 3.4e38f;
        int j1 = 0, j2 = 1;
#pragma unroll
        for (int t = 0; t < 16; ++t) {
            float d = md[tid * 16 + t];
            int ii = mi[tid * 16 + t];
            if (d < b1 || (d == b1 && ii < j1)) { b2 = b1; j2 = j1; b1 = d; j1 = ii; }
            else if (d < b2 || (d == b2 && ii < j2)) { b2 = d; j2 = ii; }
        }
        const int row = row0 + tid;
        if (row < NROWS) g_top2[row] = make_int2(j1, j2);
    }
}

// ---- phase 2: exact fp64 dists; fp32 bin-equality => ref tie => min index ----
__global__ __launch_bounds__(128, 8)
void refine_kernel(const float* __restrict__ x, const float* __restrict__ cb,
                   float* __restrict__ zq, float* __restrict__ idx_out,
                   int NROWS, int write_idx)
{
    const int warp = threadIdx.x >> 5;
    const int lane = threadIdx.x & 31;
    const int row = blockIdx.x * 4 + warp;
    if (row >= NROWS) return;

    const int2 cand = g_top2[row];
    const float* xp  = x  + (size_t)row * C_DIM + lane * 8;
    const float* e1p = cb + (size_t)cand.x * C_DIM + lane * 8;
    const float* e2p = cb + (size_t)cand.y * C_DIM + lane * 8;

    float4 xa = *(const float4*)(xp);
    float4 xb = *(const float4*)(xp + 4);
    float4 u1a = *(const float4*)(e1p);
    float4 u1b = *(const float4*)(e1p + 4);
    float4 u2a = *(const float4*)(e2p);
    float4 u2b = *(const float4*)(e2p + 4);

    double d1 = 0.0, d2 = 0.0;
    {
        const float xs[8] = {xa.x, xa.y, xa.z, xa.w, xb.x, xb.y, xb.z, xb.w};
        const float e1[8] = {u1a.x, u1a.y, u1a.z, u1a.w, u1b.x, u1b.y, u1b.z, u1b.w};
        const float e2[8] = {u2a.x, u2a.y, u2a.z, u2a.w, u2b.x, u2b.y, u2b.z, u2b.w};
#pragma unroll
        for (int t = 0; t < 8; ++t) {
            double t1 = (double)xs[t] - (double)e1[t];
            double t2 = (double)xs[t] - (double)e2[t];
            d1 = fma(t1, t1, d1);
            d2 = fma(t2, t2, d2);
        }
    }
#pragma unroll
    for (int o = 16; o > 0; o >>= 1) {
        d1 += __shfl_down_sync(0xffffffffu, d1, o);
        d2 += __shfl_down_sync(0xffffffffu, d2, o);
    }
    int chosen;
    if (lane == 0) {
        float f1 = (float)d1;
        float f2 = (float)d2;
        if (f1 == f2 || fabs(d1 - d2) < (double)TIE_GUARD) {
            chosen = min(cand.x, cand.y);
        } else {
            chosen = (f1 < f2) ? cand.x : cand.y;
        }
    }
    chosen = __shfl_sync(0xffffffffu, chosen, 0);

    const float* ep = cb + (size_t)chosen * C_DIM + lane * 8;
    float* op = zq + (size_t)row * C_DIM + lane * 8;
    *(float4*)(op)     = *(const float4*)(ep);
    *(float4*)(op + 4) = *(const float4*)(ep + 4);

    if (write_idx && lane == 0) idx_out[row] = (float)chosen;
}

extern "C" void kernel_launch(void* const* d_in, const int* in_sizes, int n_in,
                              void* d_out, int out_size) {
    const float* x  = (const float*)d_in[0];
    const float* cb = (const float*)d_in[1];
    float* out = (float*)d_out;

    const int NROWS = in_sizes[0] / C_DIM;
    const int K     = in_sizes[1] / C_DIM;

    prep_cb<<<(K + 7) / 8, 256>>>(cb, K);

    cudaFuncSetAttribute(vq_main, cudaFuncAttributeMaxDynamicSharedMemorySize, SM_TOTAL);
    vq_main<<<(NROWS + TILE_M - 1) / TILE_M, 256, SM_TOTAL>>>(x, NROWS, K);

    const int write_idx = (out_size >= NROWS * C_DIM + NROWS) ? 1 : 0;
    refine_kernel<<<(NROWS + 3) / 4, 128>>>(x, cb, out, out + (size_t)NROWS * C_DIM,
                                            NROWS, write_idx);
}

// round 12
// speedup vs baseline: 2.0682x; 1.0435x over previous
#include <cuda_runtime.h>
#include <cuda_fp16.h>
#include <cstdint>

// VQ: nearest-codebook lookup.
// Phase 1: mma.sync fp16 single-product GEMM -> global top-3 per row.
// Phase 2: exact fp64 on top-3 + fp32-bin tie emulation (verified rule),
//          candidates processed in ascending index order (jnp.argmin semantics).
// x: (N=131072, C=256), code_book: (K=1024, C=256)

#define C_DIM 256
#define TILE_M 128
#define MAXROWS 131072
#define MAXK 1024
#define TIE_GUARD 2e-6

// smem map (bytes): esq 4KB | A plane 64KB | B 2 x 16KB
#define SM_ESQ 0
#define SM_A   4096
#define SM_B   (4096 + 65536)
#define SM_TOTAL (SM_B + 32768)    // 102400 -> 2 CTAs/SM
#define SM_MERGE SM_B

__device__ float  g_esq[MAXK];
__device__ int4   g_top3[MAXROWS];
__device__ __half g_cbh[MAXK * C_DIM];

__device__ __forceinline__ uint32_t smem_u32(const void* p) {
    uint32_t a;
    asm("{ .reg .u64 t; cvta.to.shared.u64 t, %1; cvt.u32.u64 %0, t; }" : "=r"(a) : "l"(p));
    return a;
}
__device__ __forceinline__ void ldsm4(uint32_t* r, uint32_t addr) {
    asm volatile("ldmatrix.sync.aligned.m8n8.x4.shared.b16 {%0,%1,%2,%3}, [%4];"
        : "=r"(r[0]), "=r"(r[1]), "=r"(r[2]), "=r"(r[3]) : "r"(addr));
}
__device__ __forceinline__ void mma16816(float* d, const uint32_t* a, uint32_t b0, uint32_t b1) {
    asm volatile("mma.sync.aligned.m16n8k16.row.col.f32.f16.f16.f32 "
        "{%0,%1,%2,%3}, {%4,%5,%6,%7}, {%8,%9}, {%0,%1,%2,%3};"
        : "+f"(d[0]), "+f"(d[1]), "+f"(d[2]), "+f"(d[3])
        : "r"(a[0]), "r"(a[1]), "r"(a[2]), "r"(a[3]), "r"(b0), "r"(b1));
}
__device__ __forceinline__ void cp_async16(uint32_t dst, const void* src) {
    asm volatile("cp.async.cg.shared.global [%0], [%1], 16;" :: "r"(dst), "l"(src));
}
#define CP_COMMIT() asm volatile("cp.async.commit_group;" ::: "memory")
#define CP_WAIT1()  asm volatile("cp.async.wait_group 1;" ::: "memory")
#define CP_WAIT0()  asm volatile("cp.async.wait_group 0;" ::: "memory")

__device__ __forceinline__ uint32_t pkh(__half lo, __half hi) {
    return ((uint32_t)__half_as_ushort(hi) << 16) | (uint32_t)__half_as_ushort(lo);
}

// ---------------- prep: e_sq (fp32 exact) + codebook fp16 ----------------
__global__ void prep_cb(const float* __restrict__ cb, int K) {
    int k = blockIdx.x * 8 + (threadIdx.x >> 5);
    int lane = threadIdx.x & 31;
    if (k >= K) return;
    const float* p = cb + (size_t)k * C_DIM;
    float s = 0.0f;
    for (int c = lane; c < C_DIM; c += 32) {
        float f = p[c];
        s = fmaf(f, f, s);
        g_cbh[(size_t)k * C_DIM + c] = __float2half(f);
    }
#pragma unroll
    for (int o = 16; o > 0; o >>= 1) s += __shfl_down_sync(0xffffffffu, s, o);
    if (lane == 0) g_esq[k] = s;
}

// chunk = (tile, kc): 128 codes x 64 k (fp16) = 16KB
__device__ __forceinline__ void load_chunk(uint32_t sb, int ch, int tid) {
    const int tile = ch >> 2, kc = ch & 3;
    const uint32_t dstbase = sb + SM_B + (uint32_t)(ch & 1) * 16384u;
#pragma unroll
    for (int it = 0; it < 4; ++it) {
        int i = tid + it * 256;       // 0..1023 (16B units)
        int n = i >> 3;
        int jj = i & 7;
        const char* src = (const char*)g_cbh
                        + ((size_t)(tile * 128 + n) * C_DIM + kc * 64 + jj * 8) * 2;
        uint32_t dst = dstbase + (uint32_t)(n * 128 + (((jj ^ (n & 7)) << 4)));
        cp_async16(dst, src);
    }
}

// ---------------- phase 1 ----------------
__global__ __launch_bounds__(256, 2)
void vq_main(const float* __restrict__ x, int NROWS, int K)
{
    extern __shared__ char smem[];
    const uint32_t sb = smem_u32(smem);
    float* esq_s = (float*)(smem + SM_ESQ);
    const int tid = threadIdx.x;
    const int wid = tid >> 5, l = tid & 31;
    const int Wm = wid >> 1, Wn = wid & 1;
    const int row0 = blockIdx.x * TILE_M;
    const int nch = (K / 128) * 4;      // 32 for K=1024

    for (int i = tid; i < K; i += 256) esq_s[i] = g_esq[i];

    // prefetch chunk 0 while we build the A plane
    load_chunk(sb, 0, tid);
    CP_COMMIT();

    // ---- build A plane in smem (fp16, swizzled) ----
#pragma unroll 4
    for (int it = 0; it < 32; ++it) {
        int i4 = tid + it * 256;         // 8192 float4s = 128 rows x 64
        int r = i4 >> 6;
        int c0 = (i4 & 63) * 4;
        int rr = row0 + r; if (rr >= NROWS) rr = NROWS - 1;
        float4 v = *(const float4*)(x + (size_t)rr * C_DIM + c0);
        uint32_t byte = (uint32_t)(r * 512 + (((c0 >> 3) ^ (r & 7)) << 4) + (c0 & 7) * 2);
        *(uint32_t*)(smem + SM_A + byte)     = pkh(__float2half(v.x), __float2half(v.y));
        *(uint32_t*)(smem + SM_A + byte + 4) = pkh(__float2half(v.z), __float2half(v.w));
    }

    // ---- per-lane ldmatrix address bases (round-11-verified layout) ----
    uint32_t aBase[2], a7[2];
    const uint32_t jAadd = (uint32_t)((l >> 4) & 1);
#pragma unroll
    for (int mt = 0; mt < 2; ++mt) {
        int rA = Wm * 32 + mt * 16 + ((l >> 3) & 1) * 8 + (l & 7);
        aBase[mt] = sb + SM_A + (uint32_t)rA * 512u;
        a7[mt] = (uint32_t)(rA & 7) << 4;
    }
    uint32_t bOff[4], b7[4];
    const uint32_t jBadd = (uint32_t)((l >> 3) & 1);
#pragma unroll
    for (int ntp = 0; ntp < 4; ++ntp) {
        int nB = Wn * 64 + ntp * 16 + ((l >> 4) & 1) * 8 + (l & 7);
        bOff[ntp] = (uint32_t)nB * 128u;
        b7[ntp] = (uint32_t)(nB & 7) << 4;
    }

    float acc[2][8][4];
    float bd[4], sd[4];
    int bi[4], si[4];
#pragma unroll
    for (int s = 0; s < 4; ++s) { bd[s] = 3.4e38f; sd[s] = 3.4e38f; bi[s] = 0; si[s] = 1; }

    for (int ch = 0; ch < nch; ++ch) {
        if (ch + 1 < nch) { load_chunk(sb, ch + 1, tid); CP_COMMIT(); CP_WAIT1(); }
        else              { CP_WAIT0(); }
        __syncthreads();

        const int kc = ch & 3, tile = ch >> 2;
        if (kc == 0) {
#pragma unroll
            for (int mt = 0; mt < 2; ++mt)
#pragma unroll
                for (int nt = 0; nt < 8; ++nt)
#pragma unroll
                    for (int q = 0; q < 4; ++q) acc[mt][nt][q] = 0.0f;
        }
        const uint32_t bufb = sb + SM_B + (uint32_t)(ch & 1) * 16384u;

#pragma unroll
        for (int ks = 0; ks < 4; ++ks) {
            uint32_t a[2][4];
            const uint32_t jxA = (uint32_t)((kc * 8 + ks * 2 + jAadd) << 4);
#pragma unroll
            for (int mt = 0; mt < 2; ++mt)
                ldsm4(a[mt], aBase[mt] + (jxA ^ a7[mt]));

            const uint32_t jxB = (uint32_t)((ks * 2 + jBadd) << 4);
#pragma unroll
            for (int ntp = 0; ntp < 4; ++ntp) {
                uint32_t bf[4];
                ldsm4(bf, bufb + bOff[ntp] + (jxB ^ b7[ntp]));
#pragma unroll
                for (int mt = 0; mt < 2; ++mt) {
#pragma unroll
                    for (int sub = 0; sub < 2; ++sub)
                        mma16816(acc[mt][ntp * 2 + sub], a[mt], bf[2 * sub], bf[2 * sub + 1]);
                }
            }
        }

        if (kc == 3) {
            // per-source top-2 update from register accumulators
            const int cbase = tile * 128 + Wn * 64 + 2 * (l & 3);
#pragma unroll
            for (int mt = 0; mt < 2; ++mt) {
#pragma unroll
                for (int rh = 0; rh < 2; ++rh) {
                    const int s = mt * 2 + rh;
                    float lbd = bd[s], lsd = sd[s];
                    int lbi = bi[s], lsi = si[s];
#pragma unroll
                    for (int nt = 0; nt < 8; ++nt) {
                        const int code = cbase + nt * 8;
                        float d0 = fmaf(-2.0f, acc[mt][nt][rh * 2 + 0], esq_s[code]);
                        float d1 = fmaf(-2.0f, acc[mt][nt][rh * 2 + 1], esq_s[code + 1]);
                        if (d0 < lbd) { lsd = lbd; lsi = lbi; lbd = d0; lbi = code; }
                        else if (d0 < lsd) { lsd = d0; lsi = code; }
                        if (d1 < lbd) { lsd = lbd; lsi = lbi; lbd = d1; lbi = code + 1; }
                        else if (d1 < lsd) { lsd = d1; lsi = code + 1; }
                    }
                    bd[s] = lbd; sd[s] = lsd; bi[s] = lbi; si[s] = lsi;
                }
            }
        }
        __syncthreads();
    }

    // ---- merge: 8 sources x top-2 per row -> global top-3 ----
    float* md = (float*)(smem + SM_MERGE);          // [128][8][2]
    int*   mi = (int*)(smem + SM_MERGE + 8192);
#pragma unroll
    for (int mt = 0; mt < 2; ++mt) {
#pragma unroll
        for (int rh = 0; rh < 2; ++rh) {
            const int s = mt * 2 + rh;
            const int r = Wm * 32 + mt * 16 + rh * 8 + (l >> 2);
            const int slot = (l & 3) * 2 + Wn;
            md[(r * 8 + slot) * 2 + 0] = bd[s];
            md[(r * 8 + slot) * 2 + 1] = sd[s];
            mi[(r * 8 + slot) * 2 + 0] = bi[s];
            mi[(r * 8 + slot) * 2 + 1] = si[s];
        }
    }
    __syncthreads();
    if (tid < TILE_M) {
        float b1 = 3.4e38f, b2 = 3.4e38f, b3 = 3.4e38f;
        int j1 = 0, j2 = 1, j3 = 2;
#pragma unroll
        for (int t = 0; t < 16; ++t) {
            float d = md[tid * 16 + t];
            int ii = mi[tid * 16 + t];
            if (d < b1 || (d == b1 && ii < j1)) {
                b3 = b2; j3 = j2; b2 = b1; j2 = j1; b1 = d; j1 = ii;
            } else if (d < b2 || (d == b2 && ii < j2)) {
                b3 = b2; j3 = j2; b2 = d; j2 = ii;
            } else if (d < b3 || (d == b3 && ii < j3)) {
                b3 = d; j3 = ii;
            }
        }
        // sort candidate indices ascending (refine processes in index order)
        int a = j1, b = j2, c = j3, t;
        if (a > b) { t = a; a = b; b = t; }
        if (b > c) { t = b; b = c; c = t; }
        if (a > b) { t = a; a = b; b = t; }
        const int row = row0 + tid;
        if (row < NROWS) g_top3[row] = make_int4(a, b, c, 0);
    }
}

// ---- phase 2: exact fp64 on 3 candidates; fp32-bin tie => earlier index ----
__global__ __launch_bounds__(128, 8)
void refine_kernel(const float* __restrict__ x, const float* __restrict__ cb,
                   float* __restrict__ zq, float* __restrict__ idx_out,
                   int NROWS, int write_idx)
{
    const int warp = threadIdx.x >> 5;
    const int lane = threadIdx.x & 31;
    const int row = blockIdx.x * 4 + warp;
    if (row >= NROWS) return;

    const int4 cand = g_top3[row];   // indices ascending
    const float* xp = x + (size_t)row * C_DIM + lane * 8;
    float4 xa = *(const float4*)(xp);
    float4 xb = *(const float4*)(xp + 4);
    const float xs[8] = {xa.x, xa.y, xa.z, xa.w, xb.x, xb.y, xb.z, xb.w};

    double d[3];
    const int ci[3] = {cand.x, cand.y, cand.z};
#pragma unroll
    for (int q = 0; q < 3; ++q) {
        const float* ep = cb + (size_t)ci[q] * C_DIM + lane * 8;
        float4 ea = *(const float4*)(ep);
        float4 eb = *(const float4*)(ep + 4);
        const float es[8] = {ea.x, ea.y, ea.z, ea.w, eb.x, eb.y, eb.z, eb.w};
        double s = 0.0;
#pragma unroll
        for (int t = 0; t < 8; ++t) {
            double df = (double)xs[t] - (double)es[t];
            s = fma(df, df, s);
        }
        d[q] = s;
    }
#pragma unroll
    for (int o = 16; o > 0; o >>= 1) {
#pragma unroll
        for (int q = 0; q < 3; ++q)
            d[q] += __shfl_down_sync(0xffffffffu, d[q], o);
    }
    int chosen;
    if (lane == 0) {
        // ascending index order; replace only on strict (non-tie) improvement
        int bidx = ci[0];
        double bval = d[0];
#pragma unroll
        for (int q = 1; q < 3; ++q) {
            float f1 = (float)bval, f2 = (float)d[q];
            bool tie = (f1 == f2) || (fabs(d[q] - bval) < (double)TIE_GUARD);
            if (!tie && d[q] < bval) { bval = d[q]; bidx = ci[q]; }
        }
        chosen = bidx;
    }
    chosen = __shfl_sync(0xffffffffu, chosen, 0);

    const float* ep = cb + (size_t)chosen * C_DIM + lane * 8;
    float* op = zq + (size_t)row * C_DIM + lane * 8;
    *(float4*)(op)     = *(const float4*)(ep);
    *(float4*)(op + 4) = *(const float4*)(ep + 4);

    if (write_idx && lane == 0) idx_out[row] = (float)chosen;
}

extern "C" void kernel_launch(void* const* d_in, const int* in_sizes, int n_in,
                              void* d_out, int out_size) {
    const float* x  = (const float*)d_in[0];
    const float* cb = (const float*)d_in[1];
    float* out = (float*)d_out;

    const int NROWS = in_sizes[0] / C_DIM;
    const int K     = in_sizes[1] / C_DIM;

    prep_cb<<<(K + 7) / 8, 256>>>(cb, K);

    cudaFuncSetAttribute(vq_main, cudaFuncAttributeMaxDynamicSharedMemorySize, SM_TOTAL);
    vq_main<<<(NROWS + TILE_M - 1) / TILE_M, 256, SM_TOTAL>>>(x, NROWS, K);

    const int write_idx = (out_size >= NROWS * C_DIM + NROWS) ? 1 : 0;
    refine_kernel<<<(NROWS + 3) / 4, 128>>>(x, cb, out, out + (size_t)NROWS * C_DIM,
                                            NROWS, write_idx);
}